// round 17
// baseline (speedup 1.0000x reference)
#include <cuda_runtime.h>

#define BB 2
#define SS 2048
#define DD 128
#define HH 8
#define EPSF 1e-10f
#define FULLM 0xffffffffu
#define P1BLK 512                // phase-1 blocks: 4096 rows, warp per row, 256 thr
#define BPB   (P1BLK / BB)       // 256 phase-1 blocks per batch
#define NROWS (BB * HH * SS)     // 32768 output rows
#define QROW  (SS / 4)           // 512 float4 per row
#define RPB   4                  // rows per k_write block

// Scratch (allocation-free rule: __device__ globals; zero-init at load)
__device__ int      g_tt[BB * SS];
__device__ int2     g_lohi[BB * SS];
__device__ unsigned g_cnt2[BB] = {0, 0};

// ---------------------------------------------------------------------------
// Kernel 1 (grid 512 x 256): one warp per (b,s) row. Last arrival PER BATCH
// scans that batch and publishes g_lohi. PDL-trigger after g_tt contribution.
// (Unchanged from R15/R16 — validated, rel_err = 0.)
// ---------------------------------------------------------------------------
__global__ void __launch_bounds__(256) k_phase1(const float* __restrict__ x,
                                                const float* __restrict__ gu,
                                                const float* __restrict__ W,
                                                const float* __restrict__ bias) {
    const int tid = threadIdx.x;
    const int bid = blockIdx.x;

    __shared__ int sh_last;
    __shared__ int sh_wmin[8];
    __shared__ int sh_wsuf[8];

    // ---------------- argmax: warp per row ----------------
    {
        int gwarp = (bid * 256 + tid) >> 5;   // 0..4095 = b*S + s
        int lane  = tid & 31;

        const float4* xr = reinterpret_cast<const float4*>(x + (size_t)gwarp * DD);
        float4 xv = xr[lane];                 // 32 lanes * 4 = 128, coalesced

        const float4* W4 = reinterpret_cast<const float4*>(W);
        float a0, a1, a2;
        {
            float4 w0 = W4[lane];
            float4 w1 = W4[32 + lane];
            float4 w2 = W4[64 + lane];
            a0 = xv.x * w0.x + xv.y * w0.y + xv.z * w0.z + xv.w * w0.w;
            a1 = xv.x * w1.x + xv.y * w1.y + xv.z * w1.z + xv.w * w1.w;
            a2 = xv.x * w2.x + xv.y * w2.y + xv.z * w2.z + xv.w * w2.w;
        }
        #pragma unroll
        for (int off = 16; off; off >>= 1) {
            a0 += __shfl_xor_sync(FULLM, a0, off);
            a1 += __shfl_xor_sync(FULLM, a1, off);
            a2 += __shfl_xor_sync(FULLM, a2, off);
        }
        if (lane == 0) {
            const float* gr = gu + (size_t)gwarp * 3;
            float g0 = -logf(-logf(gr[0] + EPSF) + EPSF);
            float g1 = -logf(-logf(gr[1] + EPSF) + EPSF);
            float g2 = -logf(-logf(gr[2] + EPSF) + EPSF);
            float s0 = a0 + bias[0] + g0;
            float s1 = a1 + bias[1] + g1;
            float s2 = a2 + bias[2] + g2;
            int tt = 0; float best = s0;
            if (s1 > best) { best = s1; tt = 1; }   // first-max tie-break
            if (s2 > best) { best = s2; tt = 2; }
            g_tt[gwarp] = tt;
        }
    }
    __syncthreads();

    const int b = bid / BPB;                          // this block's batch
    if (tid == 0) {
        __threadfence();                              // release g_tt
        sh_last = (atomicAdd(&g_cnt2[b], 1u) == BPB - 1);
#if __CUDA_ARCH__ >= 900
        cudaTriggerProgrammaticLaunchCompletion();    // let k_write ramp
#endif
    }
    __syncthreads();
    if (!sh_last) return;

    // ------- last block of batch b: suffix-min scan, publish (lo,hi) -------
    __threadfence();                                  // acquire batch's g_tt
    int lane = tid & 31, wid = tid >> 5;              // 8 warps x 32 lanes
    {
        int base = b * SS + tid * 8;                  // 8 elems per thread
        int tts[8], e[8];
        int j0 = tid * 8;
        int m = SS;
        #pragma unroll
        for (int i = 0; i < 8; i++) {
            tts[i] = g_tt[base + i];
            e[i]   = (tts[i] == 0) ? j0 + i : SS;
            m      = min(m, e[i]);
        }

        int inc = m;                                  // warp suffix-min (inclusive)
        #pragma unroll
        for (int off = 1; off < 32; off <<= 1) {
            int v = __shfl_down_sync(FULLM, inc, off);
            if (lane + off < 32) inc = min(inc, v);
        }
        int excl = __shfl_down_sync(FULLM, inc, 1);
        if (lane == 31) excl = SS;

        if (lane == 0) sh_wmin[wid] = inc;
        __syncthreads();
        if (wid == 0) {
            int wm = (lane < 8) ? sh_wmin[lane] : SS;
            int winc = wm;
            #pragma unroll
            for (int off = 1; off < 8; off <<= 1) {
                int v = __shfl_down_sync(FULLM, winc, off);
                if (lane + off < 8) winc = min(winc, v);
            }
            int wex = __shfl_down_sync(FULLM, winc, 1);  // lane7 gets lane8's SS
            if (lane < 8) sh_wsuf[lane] = wex;
        }
        __syncthreads();
        int after = min(excl, sh_wsuf[wid]);          // min over idx > j0+7

        int run = after;                              // right-to-left next_global
        int ng[8];
        #pragma unroll
        for (int i = 7; i >= 0; i--) {
            ng[i] = run;
            run   = min(run, e[i]);
        }

        #pragma unroll
        for (int i = 0; i < 8; i++) {
            int j = j0 + i;
            int2 lh; lh.x = 0; lh.y = j;
            if (tts[i] == 1)      { lh.x = j; lh.y = j; }
            else if (tts[i] == 2) { lh.y = min(j, ng[i]); }
            g_lohi[base + i] = lh;
        }
    }
    __syncthreads();
    if (tid == 0) g_cnt2[b] = 0;        // reset for next graph replay
}

// ---------------------------------------------------------------------------
// Kernel 2: FOUR adjacent rows per block (contiguous 32KB span), 256 threads,
// 8 independent float4 stores per thread, lohi loads up-front (MLP=4).
// PDL sync before reading g_lohi.
// ---------------------------------------------------------------------------
__global__ void __launch_bounds__(256) k_write(float4* __restrict__ out) {
    int row0 = blockIdx.x * RPB;         // rows row0..row0+3 (same b,h)
    int s0   = row0 & (SS - 1);
    int b    = row0 >> 14;               // / (H*S)
    int tid  = threadIdx.x;

#if __CUDA_ARCH__ >= 900
    cudaGridDependencySynchronize();     // all phase-1 memory visible
#endif

    int2 lh[RPB];
    #pragma unroll
    for (int r = 0; r < RPB; r++) lh[r] = g_lohi[b * SS + s0 + r];  // MLP=4

    float4* orow = out + (size_t)row0 * QROW;   // 2048 contiguous quads
    #pragma unroll
    for (int it = 0; it < 2; it++) {
        int q = it * 256 + tid;
        int j = q << 2;
        #pragma unroll
        for (int r = 0; r < RPB; r++) {
            float4 v;
            v.x = (j     >= lh[r].x && j     <= lh[r].y) ? 1.0f : 0.0f;
            v.y = (j + 1 >= lh[r].x && j + 1 <= lh[r].y) ? 1.0f : 0.0f;
            v.z = (j + 2 >= lh[r].x && j + 2 <= lh[r].y) ? 1.0f : 0.0f;
            v.w = (j + 3 >= lh[r].x && j + 3 <= lh[r].y) ? 1.0f : 0.0f;
            orow[(size_t)r * QROW + q] = v;
        }
    }
}

extern "C" void kernel_launch(void* const* d_in, const int* in_sizes, int n_in,
                              void* d_out, int out_size) {
    const float* x    = (const float*)d_in[0];  // input_tensor (B,S,D)
    // d_in[1] = token_types (unused by reference)
    const float* gu   = (const float*)d_in[2];  // gumbel_u (B,S,3)
    const float* W    = (const float*)d_in[3];  // (3,D)
    const float* bias = (const float*)d_in[4];  // (3,)
    float4* out = (float4*)d_out;

    k_phase1<<<P1BLK, 256>>>(x, gu, W, bias);

    // k_write with programmatic dependent launch (overlaps phase-1 tail).
    cudaLaunchConfig_t cfg = {};
    cfg.gridDim  = dim3(NROWS / RPB, 1, 1);
    cfg.blockDim = dim3(256, 1, 1);
    cfg.dynamicSmemBytes = 0;
    cfg.stream = 0;
    cudaLaunchAttribute attr[1];
    attr[0].id = cudaLaunchAttributeProgrammaticStreamSerialization;
    attr[0].val.programmaticStreamSerializationAllowed = 1;
    cfg.attrs = attr;
    cfg.numAttrs = 1;
    cudaLaunchKernelEx(&cfg, k_write, out);
}